// round 1
// baseline (speedup 1.0000x reference)
#include <cuda_runtime.h>
#include <cstdint>

// ---------------- problem constants ----------------
#define L_T   16
#define BSZ   8
#define H_    32
#define W_    32
#define U_    128
#define P_    256
#define FRAMES (L_T*BSZ)          // 128
#define SP    (BSZ*H_*W_*P_)      // 2,097,152  (per-l complex-plane element count)
#define YS_N  (L_T*BSZ*H_*W_*U_)  // 16,777,216
#define BUS_N (L_T*BSZ*H_*W_*P_)  // 33,554,432
#define WB_N  (9*U_*P_)           // 294,912
#define EPS_GN 1e-5f

// ---------------- device scratch (allocation-free) ----------------
__device__ float g_Wb_re[WB_N];   // [ky*3+kx][u][p]  (p fastest)
__device__ float g_Wb_im[WB_N];
__device__ float g_Wc_re[WB_N];   // [ky*3+kx][p][u]  (u fastest)
__device__ float g_Wc_im[WB_N];
__device__ float g_Are[P_];
__device__ float g_Aim[P_];
__device__ float g_Bus_re[BUS_N];
__device__ float g_Bus_im[BUS_N];
__device__ float g_ys[YS_N];

// ---------------- K0: discretization + weight relayout ----------------
__global__ void k_pre(const float* __restrict__ Lre, const float* __restrict__ Lim,
                      const float* __restrict__ lstep,
                      const float* __restrict__ B_ri, const float* __restrict__ C_ri) {
    int tid = blockIdx.x * blockDim.x + threadIdx.x;
    if (tid < WB_N) {
        // tid = k9*32768 + u*256 + p
        int p  = tid & 255;
        int u  = (tid >> 8) & 127;
        int k9 = tid >> 15;
        float st = expf(lstep[p]);
        size_t src = ((size_t)(p * U_ + u) * 9 + k9) * 2;   // B_ri (P,U,3,3,2)
        g_Wb_re[tid] = B_ri[src]     * st;
        g_Wb_im[tid] = B_ri[src + 1] * st;
    } else if (tid < 2 * WB_N) {
        int t  = tid - WB_N;
        // t = k9*32768 + p*128 + u
        int u  = t & 127;
        int p  = (t >> 7) & 255;
        int k9 = t >> 15;
        size_t src = ((size_t)(u * P_ + p) * 9 + k9) * 2;   // C_ri (U,P,3,3,2)
        g_Wc_re[t] = C_ri[src];
        g_Wc_im[t] = C_ri[src + 1];
    }
    if (tid < P_) {
        float st = expf(lstep[tid]);
        float lr = fminf(Lre[tid], -1e-4f);
        g_Are[tid] = lr * st;
        g_Aim[tid] = Lim[tid] * st;
    }
}

// ---------------- K1: complex B-conv (U=128 -> P=256), + A_bar*x0 at l==0 ----
// block = (frame, row). 256 threads, one per p. Each thread makes a full W row.
__global__ __launch_bounds__(256) void k_convB(const float* __restrict__ u_in,
                                               const float* __restrict__ x0) {
    int f = blockIdx.x;       // frame = l*BSZ + b
    int y = blockIdx.y;
    int p = threadIdx.x;
    __shared__ float s_in[34 * U_];

    float accr[W_], acci[W_];
#pragma unroll
    for (int x = 0; x < W_; x++) { accr[x] = 0.f; acci[x] = 0.f; }

    for (int ky = 0; ky < 3; ky++) {
        int yi = y + ky - 1;
        __syncthreads();
        if (yi >= 0 && yi < H_) {
            const float* row = u_in + ((size_t)(f * H_ + yi) * W_) * U_;
            for (int i = p; i < 34 * U_; i += 256) {
                int xx = i >> 7, uu = i & 127, xg = xx - 1;
                s_in[i] = (xg >= 0 && xg < W_) ? row[xg * U_ + uu] : 0.f;
            }
        } else {
            for (int i = p; i < 34 * U_; i += 256) s_in[i] = 0.f;
        }
        __syncthreads();

        const float* wbr = g_Wb_re + ky * (3 * U_ * P_) + p;
        const float* wbi = g_Wb_im + ky * (3 * U_ * P_) + p;
#pragma unroll 1
        for (int uu = 0; uu < U_; uu++) {
            int o = uu * P_;
            float br0 = wbr[o], br1 = wbr[o + U_ * P_], br2 = wbr[o + 2 * U_ * P_];
            float bi0 = wbi[o], bi1 = wbi[o + U_ * P_], bi2 = wbi[o + 2 * U_ * P_];
            float v0 = s_in[uu];
            float v1 = s_in[U_ + uu];
#pragma unroll
            for (int x = 0; x < W_; x++) {
                float v2 = s_in[(x + 2) * U_ + uu];
                accr[x] = fmaf(v0, br0, fmaf(v1, br1, fmaf(v2, br2, accr[x])));
                acci[x] = fmaf(v0, bi0, fmaf(v1, bi1, fmaf(v2, bi2, acci[x])));
                v0 = v1; v1 = v2;
            }
        }
    }

    // l==0 frames (f < BSZ): Bus[0] += A_bar * x0  (x0 real)
    if (f < BSZ) {
        float ar = g_Are[p], ai = g_Aim[p];
        const float* x0row = x0 + ((size_t)(f * H_ + y) * W_) * P_ + p;
#pragma unroll
        for (int x = 0; x < W_; x++) {
            float v = x0row[x * P_];
            accr[x] = fmaf(ar, v, accr[x]);
            acci[x] = fmaf(ai, v, acci[x]);
        }
    }

    size_t base = ((size_t)(f * H_ + y) * W_) * P_ + p;
#pragma unroll
    for (int x = 0; x < W_; x++) {
        g_Bus_re[base + (size_t)x * P_] = accr[x];
        g_Bus_im[base + (size_t)x * P_] = acci[x];
    }
}

// ---------------- K2: diagonal complex scan over L, writes x_last to d_out ----
__global__ __launch_bounds__(256) void k_scan(float* __restrict__ out) {
    int s = blockIdx.x * 256 + threadIdx.x;     // < SP
    int p = s & 255;
    float ar = g_Are[p], ai = g_Aim[p];
    float xr = 0.f, xi = 0.f;
    size_t idx = (size_t)s;
#pragma unroll
    for (int l = 0; l < L_T; l++, idx += SP) {
        float br = g_Bus_re[idx], bi = g_Bus_im[idx];
        float nr = fmaf(ar, xr, fmaf(-ai, xi, br));
        float ni = fmaf(ar, xi, fmaf( ai, xr, bi));
        xr = nr; xi = ni;
        g_Bus_re[idx] = xr;
        g_Bus_im[idx] = xi;
    }
    // x_last_ri region: first SP complex pairs of d_out, layout (b,y,x,p,2)
    reinterpret_cast<float2*>(out)[s] = make_float2(xr, xi);
}

// ---------------- K3: complex C-conv (P=256 -> U=128), *2, + depthwise D ----
// block = (frame, row). 128 threads, one per u.
__global__ __launch_bounds__(128) void k_convC(const float* __restrict__ u_in,
                                               const float* __restrict__ Dk) {
    int f = blockIdx.x;
    int y = blockIdx.y;
    int u = threadIdx.x;
    __shared__ float s_xr[34 * 128];
    __shared__ float s_xi[34 * 128];

    float acc[W_];
#pragma unroll
    for (int x = 0; x < W_; x++) acc[x] = 0.f;

    for (int pc = 0; pc < 2; pc++) {
        for (int ky = 0; ky < 3; ky++) {
            int yi = y + ky - 1;
            __syncthreads();
            if (yi >= 0 && yi < H_) {
                size_t rb = ((size_t)(f * H_ + yi) * W_) * P_ + pc * 128;
                for (int i = u; i < 34 * 128; i += 128) {
                    int xx = i >> 7, pp = i & 127, xg = xx - 1;
                    float vr = 0.f, vi = 0.f;
                    if (xg >= 0 && xg < W_) {
                        size_t idx = rb + (size_t)xg * P_ + pp;
                        vr = g_Bus_re[idx];
                        vi = g_Bus_im[idx];
                    }
                    s_xr[i] = vr; s_xi[i] = vi;
                }
            } else {
                for (int i = u; i < 34 * 128; i += 128) { s_xr[i] = 0.f; s_xi[i] = 0.f; }
            }
            __syncthreads();

            const float* wcr = g_Wc_re + ky * (3 * P_ * U_) + pc * (128 * U_) + u;
            const float* wci = g_Wc_im + ky * (3 * P_ * U_) + pc * (128 * U_) + u;
#pragma unroll 1
            for (int pl = 0; pl < 128; pl++) {
                int o = pl * U_;
                float cr0 =  wcr[o], cr1 =  wcr[o + P_ * U_], cr2 =  wcr[o + 2 * P_ * U_];
                float ci0 = -wci[o], ci1 = -wci[o + P_ * U_], ci2 = -wci[o + 2 * P_ * U_];
                float vr0 = s_xr[pl],        vr1 = s_xr[128 + pl];
                float vi0 = s_xi[pl],        vi1 = s_xi[128 + pl];
#pragma unroll
                for (int x = 0; x < W_; x++) {
                    float vr2 = s_xr[(x + 2) * 128 + pl];
                    float vi2 = s_xi[(x + 2) * 128 + pl];
                    float a = acc[x];
                    a = fmaf(vr0, cr0, a);
                    a = fmaf(vr1, cr1, a);
                    a = fmaf(vr2, cr2, a);
                    a = fmaf(vi0, ci0, a);
                    a = fmaf(vi1, ci1, a);
                    a = fmaf(vi2, ci2, a);
                    acc[x] = a;
                    vr0 = vr1; vr1 = vr2; vi0 = vi1; vi1 = vi2;
                }
            }
        }
    }

    // ys = 2*conv ; then add depthwise D feedthrough
#pragma unroll
    for (int x = 0; x < W_; x++) acc[x] *= 2.f;

    float dk[9];
#pragma unroll
    for (int j = 0; j < 9; j++) dk[j] = Dk[j * U_ + u];
    for (int ky = 0; ky < 3; ky++) {
        int yi = y + ky - 1;
        if (yi < 0 || yi >= H_) continue;
        const float* row = u_in + ((size_t)(f * H_ + yi) * W_) * U_ + u;
        float v0 = 0.f;
        float v1 = row[0];
#pragma unroll
        for (int x = 0; x < W_; x++) {
            float v2 = (x + 1 < W_) ? row[(x + 1) * U_] : 0.f;
            acc[x] = fmaf(v0, dk[ky * 3 + 0], fmaf(v1, dk[ky * 3 + 1], fmaf(v2, dk[ky * 3 + 2], acc[x])));
            v0 = v1; v1 = v2;
        }
    }

    size_t base = ((size_t)(f * H_ + y) * W_) * U_ + u;
#pragma unroll
    for (int x = 0; x < W_; x++) g_ys[base + (size_t)x * U_] = acc[x];
}

// ---------------- K4: GroupNorm(32 groups) + tanh-GELU -> d_out ys region ----
__global__ __launch_bounds__(256) void k_gn(const float* __restrict__ scale,
                                            const float* __restrict__ bias,
                                            float* __restrict__ out) {
    int f = blockIdx.x;     // frame
    int g = blockIdx.y;     // group (4 channels each)
    size_t base = (size_t)f * (H_ * W_ * U_) + g * 4;

    float s = 0.f, s2 = 0.f;
    for (int j = threadIdx.x; j < H_ * W_ * 4; j += 256) {
        int yx = j >> 2, cl = j & 3;
        float v = g_ys[base + (size_t)yx * U_ + cl];
        s += v; s2 += v * v;
    }
    __shared__ float rs[8], rs2[8];
    unsigned m = 0xffffffffu;
#pragma unroll
    for (int o = 16; o > 0; o >>= 1) {
        s  += __shfl_down_sync(m, s,  o);
        s2 += __shfl_down_sync(m, s2, o);
    }
    if ((threadIdx.x & 31) == 0) { rs[threadIdx.x >> 5] = s; rs2[threadIdx.x >> 5] = s2; }
    __syncthreads();
    if (threadIdx.x == 0) {
        float ts = 0.f, ts2 = 0.f;
#pragma unroll
        for (int i = 0; i < 8; i++) { ts += rs[i]; ts2 += rs2[i]; }
        float mu  = ts * (1.f / 4096.f);
        float var = ts2 * (1.f / 4096.f) - mu * mu;
        rs[0]  = mu;
        rs2[0] = rsqrtf(var + EPS_GN);
    }
    __syncthreads();
    float mu = rs[0], rstd = rs2[0];

    float sc[4], bi[4];
#pragma unroll
    for (int c = 0; c < 4; c++) { sc[c] = scale[g * 4 + c]; bi[c] = bias[g * 4 + c]; }

    float* outy = out + (size_t)SP * 2;   // after x_last_ri region
    for (int j = threadIdx.x; j < H_ * W_ * 4; j += 256) {
        int yx = j >> 2, cl = j & 3;
        size_t idx = base + (size_t)yx * U_ + cl;
        float v = g_ys[idx];
        float h = (v - mu) * rstd * sc[cl] + bi[cl];
        // tanh-approximate GELU (jax.nn.gelu default)
        float t = 0.7978845608028654f * (h + 0.044715f * h * h * h);
        float gelu = 0.5f * h * (1.f + tanhf(t));
        outy[idx] = gelu;
    }
}

// ---------------- launch ----------------
extern "C" void kernel_launch(void* const* d_in, const int* in_sizes, int n_in,
                              void* d_out, int out_size) {
    const float* u_in  = (const float*)d_in[0];   // (L,B,H,W,U)
    const float* x0    = (const float*)d_in[1];   // (B,H,W,P)
    const float* Lre   = (const float*)d_in[2];
    const float* Lim   = (const float*)d_in[3];
    const float* B_ri  = (const float*)d_in[4];
    const float* C_ri  = (const float*)d_in[5];
    const float* lstep = (const float*)d_in[6];
    const float* Dk    = (const float*)d_in[7];
    const float* gsc   = (const float*)d_in[8];
    const float* gbi   = (const float*)d_in[9];
    float* out = (float*)d_out;
    (void)in_sizes; (void)n_in; (void)out_size;

    k_pre<<<(2 * WB_N + 255) / 256, 256>>>(Lre, Lim, lstep, B_ri, C_ri);

    dim3 gconv(FRAMES, H_);
    k_convB<<<gconv, 256>>>(u_in, x0);
    k_scan<<<SP / 256, 256>>>(out);
    k_convC<<<gconv, 128>>>(u_in, Dk);

    dim3 ggn(FRAMES, 32);
    k_gn<<<ggn, 256>>>(gsc, gbi, out);
}

// round 3
// speedup vs baseline: 2.9070x; 2.9070x over previous
#include <cuda_runtime.h>
#include <cstdint>

// ---------------- problem constants ----------------
#define L_T   16
#define BSZ   8
#define H_    32
#define W_    32
#define U_    128
#define P_    256
#define FRAMES 128
#define SP    (BSZ*H_*W_*P_)      // 2,097,152
#define YS_N  (L_T*BSZ*H_*W_*U_)  // 16,777,216
#define BUS_N (L_T*BSZ*H_*W_*P_)  // 33,554,432
#define EPS_GN 1e-5f

#define NB_W  589824              // 36 chunks x 4 nblk x 16 ntl x 4 kk x 32 lane x 2
#define NC_W  589824              // 144 chunks x 16 ntl x 4 kk x 32 lane x 2

// ---------------- device scratch (allocation-free) ----------------
__device__ __align__(16) float g_WB[NB_W];
__device__ __align__(16) float g_WC[NC_W];
__device__ float g_Are[P_];
__device__ float g_Aim[P_];
__device__ __align__(16) float g_Bus_re[BUS_N];
__device__ __align__(16) float g_Bus_im[BUS_N];
__device__ __align__(16) float g_ys[YS_N];

__device__ __forceinline__ uint32_t f2tf(float f) {
    uint32_t r; asm("cvt.rna.tf32.f32 %0, %1;" : "=r"(r) : "f"(f)); return r;
}

#define MMA_TF32(c, a, b) asm volatile( \
    "mma.sync.aligned.m16n8k8.row.col.f32.tf32.tf32.f32 " \
    "{%0,%1,%2,%3},{%4,%5,%6,%7},{%8,%9},{%0,%1,%2,%3};" \
    : "+f"((c)[0]), "+f"((c)[1]), "+f"((c)[2]), "+f"((c)[3]) \
    : "r"((a).x), "r"((a).y), "r"((a).z), "r"((a).w), "r"((b).x), "r"((b).y))

// ---------------- K0: discretization + weight fragment pre-permute ---------
// WB fragment value at flat index tid:
//   e=tid&1, lane=(tid>>1)&31, kk=(tid>>6)&3, ntl=(tid>>8)&15, nb=(tid>>12)&3, chunk=tid>>14
//   n = nb*128 + ntl*8 + (lane>>2)   (n<256: re plane, else im)
//   k = chunk*32 + kk*8 + (lane&3) + 4*e ; tap=k>>7, c=k&127
__global__ void k_pre(const float* __restrict__ Lre, const float* __restrict__ Lim,
                      const float* __restrict__ lstep,
                      const float* __restrict__ B_ri, const float* __restrict__ C_ri) {
    int tid = blockIdx.x * blockDim.x + threadIdx.x;
    if (tid < P_) {
        float st = expf(lstep[tid]);
        g_Are[tid] = fminf(Lre[tid], -1e-4f) * st;
        g_Aim[tid] = Lim[tid] * st;
    }
    if (tid < NB_W) {
        int e = tid & 1, lane = (tid >> 1) & 31, kk = (tid >> 6) & 3;
        int ntl = (tid >> 8) & 15, nb = (tid >> 12) & 3, chunk = tid >> 14;
        int n = nb * 128 + ntl * 8 + (lane >> 2);
        int k = chunk * 32 + kk * 8 + (lane & 3) + 4 * e;
        int tap = k >> 7, c = k & 127;
        int plane = n >> 8, p = n & 255;
        float v = B_ri[(((size_t)p * 128 + c) * 9 + tap) * 2 + plane] * expf(lstep[p]);
        g_WB[tid] = __uint_as_float(f2tf(v));
    }
    int t2 = tid - NB_W;
    if (t2 >= 0 && t2 < NC_W) {
        int e = t2 & 1, lane = (t2 >> 1) & 31, kk = (t2 >> 6) & 3;
        int ntl = (t2 >> 8) & 15, chunk = t2 >> 12;          // 0..143
        int u = ntl * 8 + (lane >> 2);
        int tap = chunk >> 4;
        int cidx = (chunk & 15) * 32 + kk * 8 + (lane & 3) + 4 * e;  // 0..511
        float v;
        if (cidx < 256) v =  2.f * C_ri[(((size_t)u * 256 + cidx) * 9 + tap) * 2];
        else            v = -2.f * C_ri[(((size_t)u * 256 + (cidx - 256)) * 9 + tap) * 2 + 1];
        g_WC[t2] = __uint_as_float(f2tf(v));
    }
}

// ---------------- GEMM B: Bus(re|im) = u (*) B_bar, tf32 mma.sync ----------
// grid (nb=4, slab=8, f=128). BM=128 px (4 rows), BN=128, BK=32, K=1152.
__global__ __launch_bounds__(256) void k_gemmB(const float* __restrict__ u_in) {
    extern __shared__ float sm[];
    float* As = sm;            // [2][4096] fragment layout
    float* Ws = sm + 8192;     // [2][4096]
    int tid = threadIdx.x, lane = tid & 31, wid = tid >> 5;
    int wm = wid >> 2, wn = wid & 3;
    int g8 = lane >> 2, tig = lane & 3;
    int kkf = (tid >> 5) & 3, mhi = tid >> 7;
    int nb = blockIdx.x, slab = blockIdx.y, f = blockIdx.z;
    int y0 = slab * 4;

    float acc[4][4][4];
#pragma unroll
    for (int i = 0; i < 4; i++)
#pragma unroll
        for (int j = 0; j < 4; j++)
#pragma unroll
            for (int e = 0; e < 4; e++) acc[i][j][e] = 0.f;

    float4 ra[4], rw[4];

#define LOAD_REGS_B(k) do { \
    int tap = (k) >> 2, c0 = ((k) & 3) * 32; \
    int ky = tap / 3 - 1, kx = tap % 3 - 1; \
    int c = c0 + kkf * 8 + tig; \
    _Pragma("unroll") \
    for (int q = 0; q < 4; q++) { \
        int mt = 2 * q + mhi; \
        int m1 = mt * 16 + g8, m2 = m1 + 8; \
        int y1 = y0 + (m1 >> 5) + ky, x1 = (m1 & 31) + kx; \
        int y2 = y0 + (m2 >> 5) + ky, x2 = (m2 & 31) + kx; \
        bool ok1 = ((unsigned)y1 < 32u) && ((unsigned)x1 < 32u); \
        bool ok2 = ((unsigned)y2 < 32u) && ((unsigned)x2 < 32u); \
        const float* p1 = u_in + (((size_t)f * 32 + y1) * 32 + x1) * 128 + c; \
        const float* p2 = u_in + (((size_t)f * 32 + y2) * 32 + x2) * 128 + c; \
        ra[q].x = ok1 ? p1[0] : 0.f;  ra[q].z = ok1 ? p1[4] : 0.f; \
        ra[q].y = ok2 ? p2[0] : 0.f;  ra[q].w = ok2 ? p2[4] : 0.f; \
    } \
    const float4* wsrc = (const float4*)(g_WB + ((size_t)(k) * 4 + nb) * 4096); \
    _Pragma("unroll") \
    for (int q = 0; q < 4; q++) rw[q] = wsrc[q * 256 + tid]; \
} while (0)

#define STORE_SMEM(buf) do { \
    _Pragma("unroll") \
    for (int q = 0; q < 4; q++) { \
        int mt = 2 * q + mhi; \
        uint4 t = make_uint4(f2tf(ra[q].x), f2tf(ra[q].y), f2tf(ra[q].z), f2tf(ra[q].w)); \
        *(uint4*)(As + (buf) * 4096 + ((mt * 4 + kkf) << 7) + (lane << 2)) = t; \
    } \
    float4* wdst = (float4*)(Ws + (buf) * 4096); \
    _Pragma("unroll") \
    for (int q = 0; q < 4; q++) wdst[q * 256 + tid] = rw[q]; \
} while (0)

#define COMPUTE(buf) do { \
    const float* Ab = As + (buf) * 4096 + (wm << 11); \
    const float* Wb = Ws + (buf) * 4096 + (wn << 10); \
    _Pragma("unroll") \
    for (int kk = 0; kk < 4; kk++) { \
        uint4 a[4]; uint2 b[4]; \
        _Pragma("unroll") \
        for (int mt = 0; mt < 4; mt++) a[mt] = *(const uint4*)(Ab + ((mt * 4 + kk) << 7) + (lane << 2)); \
        _Pragma("unroll") \
        for (int nt = 0; nt < 4; nt++) b[nt] = *(const uint2*)(Wb + ((nt * 4 + kk) << 6) + (lane << 1)); \
        _Pragma("unroll") \
        for (int mt = 0; mt < 4; mt++) \
            _Pragma("unroll") \
            for (int nt = 0; nt < 4; nt++) MMA_TF32(acc[mt][nt], a[mt], b[nt]); \
    } \
} while (0)

    LOAD_REGS_B(0); STORE_SMEM(0); __syncthreads();
    for (int k = 0; k < 36; k++) {
        if (k + 1 < 36) LOAD_REGS_B(k + 1);
        COMPUTE(k & 1);
        if (k + 1 < 36) STORE_SMEM((k + 1) & 1);
        __syncthreads();
    }

    float* base = (nb < 2) ? g_Bus_re : g_Bus_im;
    int ch0 = (nb & 1) * 128 + wn * 32;
#pragma unroll
    for (int mt = 0; mt < 4; mt++) {
        int m1 = wm * 64 + mt * 16 + g8, m2 = m1 + 8;
        size_t pix1 = (((size_t)f * 32 + y0 + (m1 >> 5)) * 32 + (m1 & 31)) * 256;
        size_t pix2 = (((size_t)f * 32 + y0 + (m2 >> 5)) * 32 + (m2 & 31)) * 256;
#pragma unroll
        for (int nt = 0; nt < 4; nt++) {
            int ch = ch0 + nt * 8 + tig * 2;
            *(float2*)(base + pix1 + ch) = make_float2(acc[mt][nt][0], acc[mt][nt][1]);
            *(float2*)(base + pix2 + ch) = make_float2(acc[mt][nt][2], acc[mt][nt][3]);
        }
    }
}

// ---------------- K2: diagonal complex scan, x0 init, x_last -> d_out ------
__global__ __launch_bounds__(256) void k_scan(const float* __restrict__ x0,
                                              float* __restrict__ out) {
    int s = blockIdx.x * 256 + threadIdx.x;
    int p = s & 255;
    float ar = g_Are[p], ai = g_Aim[p];
    float xr = x0[s], xi = 0.f;
    size_t idx = (size_t)s;
#pragma unroll
    for (int l = 0; l < L_T; l++, idx += SP) {
        float br = g_Bus_re[idx], bi = g_Bus_im[idx];
        float nr = fmaf(ar, xr, fmaf(-ai, xi, br));
        float ni = fmaf(ar, xi, fmaf(ai, xr, bi));
        xr = nr; xi = ni;
        g_Bus_re[idx] = xr;
        g_Bus_im[idx] = xi;
    }
    reinterpret_cast<float2*>(out)[s] = make_float2(xr, xi);
}

// ---------------- GEMM C: ys = 2Re(C (*) x), tf32 mma.sync -----------------
// grid (slab=8, f=128). BN=128, K=4608 (144 chunks: tap*16 + kc; kc<8 re, else im).
__global__ __launch_bounds__(256) void k_gemmC(int dummy) {
    extern __shared__ float sm[];
    float* As = sm;
    float* Ws = sm + 8192;
    int tid = threadIdx.x, lane = tid & 31, wid = tid >> 5;
    int wm = wid >> 2, wn = wid & 3;
    int g8 = lane >> 2, tig = lane & 3;
    int kkf = (tid >> 5) & 3, mhi = tid >> 7;
    int slab = blockIdx.x, f = blockIdx.y;
    int y0 = slab * 4;

    float acc[4][4][4];
#pragma unroll
    for (int i = 0; i < 4; i++)
#pragma unroll
        for (int j = 0; j < 4; j++)
#pragma unroll
            for (int e = 0; e < 4; e++) acc[i][j][e] = 0.f;

    float4 ra[4], rw[4];

#define LOAD_REGS_C(k) do { \
    int tap = (k) >> 4, kc = (k) & 15; \
    const float* src = (kc < 8) ? g_Bus_re : g_Bus_im; \
    int c0 = (kc & 7) * 32; \
    int ky = tap / 3 - 1, kx = tap % 3 - 1; \
    int c = c0 + kkf * 8 + tig; \
    _Pragma("unroll") \
    for (int q = 0; q < 4; q++) { \
        int mt = 2 * q + mhi; \
        int m1 = mt * 16 + g8, m2 = m1 + 8; \
        int y1 = y0 + (m1 >> 5) + ky, x1 = (m1 & 31) + kx; \
        int y2 = y0 + (m2 >> 5) + ky, x2 = (m2 & 31) + kx; \
        bool ok1 = ((unsigned)y1 < 32u) && ((unsigned)x1 < 32u); \
        bool ok2 = ((unsigned)y2 < 32u) && ((unsigned)x2 < 32u); \
        const float* p1 = src + (((size_t)f * 32 + y1) * 32 + x1) * 256 + c; \
        const float* p2 = src + (((size_t)f * 32 + y2) * 32 + x2) * 256 + c; \
        ra[q].x = ok1 ? p1[0] : 0.f;  ra[q].z = ok1 ? p1[4] : 0.f; \
        ra[q].y = ok2 ? p2[0] : 0.f;  ra[q].w = ok2 ? p2[4] : 0.f; \
    } \
    const float4* wsrc = (const float4*)(g_WC + (size_t)(k) * 4096); \
    _Pragma("unroll") \
    for (int q = 0; q < 4; q++) rw[q] = wsrc[q * 256 + tid]; \
} while (0)

    LOAD_REGS_C(0); STORE_SMEM(0); __syncthreads();
    for (int k = 0; k < 144; k++) {
        if (k + 1 < 144) LOAD_REGS_C(k + 1);
        COMPUTE(k & 1);
        if (k + 1 < 144) STORE_SMEM((k + 1) & 1);
        __syncthreads();
    }

#pragma unroll
    for (int mt = 0; mt < 4; mt++) {
        int m1 = wm * 64 + mt * 16 + g8, m2 = m1 + 8;
        size_t pix1 = (((size_t)f * 32 + y0 + (m1 >> 5)) * 32 + (m1 & 31)) * 128;
        size_t pix2 = (((size_t)f * 32 + y0 + (m2 >> 5)) * 32 + (m2 & 31)) * 128;
#pragma unroll
        for (int nt = 0; nt < 4; nt++) {
            int ch = wn * 32 + nt * 8 + tig * 2;
            *(float2*)(g_ys + pix1 + ch) = make_float2(acc[mt][nt][0], acc[mt][nt][1]);
            *(float2*)(g_ys + pix2 + ch) = make_float2(acc[mt][nt][2], acc[mt][nt][3]);
        }
    }
    (void)dummy;
}

// ---------------- K3b: depthwise D feedthrough, ys += D (*) u --------------
__global__ __launch_bounds__(128) void k_dw(const float* __restrict__ u_in,
                                            const float* __restrict__ Dk) {
    int f = blockIdx.x, y = blockIdx.y, u = threadIdx.x;
    float dk[9];
#pragma unroll
    for (int j = 0; j < 9; j++) dk[j] = Dk[j * U_ + u];
    float acc[W_];
#pragma unroll
    for (int x = 0; x < W_; x++) acc[x] = 0.f;
    for (int ky = 0; ky < 3; ky++) {
        int yi = y + ky - 1;
        if (yi < 0 || yi >= H_) continue;
        const float* row = u_in + ((size_t)(f * H_ + yi) * W_) * U_ + u;
        float v0 = 0.f, v1 = row[0];
#pragma unroll
        for (int x = 0; x < W_; x++) {
            float v2 = (x + 1 < W_) ? row[(x + 1) * U_] : 0.f;
            acc[x] = fmaf(v0, dk[ky * 3], fmaf(v1, dk[ky * 3 + 1], fmaf(v2, dk[ky * 3 + 2], acc[x])));
            v0 = v1; v1 = v2;
        }
    }
    size_t base = ((size_t)(f * H_ + y) * W_) * U_ + u;
#pragma unroll
    for (int x = 0; x < W_; x++) g_ys[base + (size_t)x * U_] += acc[x];
}

// ---------------- K4: GroupNorm(32) + tanh-GELU -> d_out ys region --------
__global__ __launch_bounds__(256) void k_gn(const float* __restrict__ scale,
                                            const float* __restrict__ bias,
                                            float* __restrict__ out) {
    int f = blockIdx.x, g = blockIdx.y;
    size_t base = (size_t)f * (H_ * W_ * U_) + g * 4;

    float s = 0.f, s2 = 0.f;
    for (int j = threadIdx.x; j < H_ * W_ * 4; j += 256) {
        int yx = j >> 2, cl = j & 3;
        float v = g_ys[base + (size_t)yx * U_ + cl];
        s += v; s2 += v * v;
    }
    __shared__ float rs[8], rs2[8];
    unsigned m = 0xffffffffu;
#pragma unroll
    for (int o = 16; o > 0; o >>= 1) {
        s  += __shfl_down_sync(m, s, o);
        s2 += __shfl_down_sync(m, s2, o);
    }
    if ((threadIdx.x & 31) == 0) { rs[threadIdx.x >> 5] = s; rs2[threadIdx.x >> 5] = s2; }
    __syncthreads();
    if (threadIdx.x == 0) {
        float ts = 0.f, ts2 = 0.f;
#pragma unroll
        for (int i = 0; i < 8; i++) { ts += rs[i]; ts2 += rs2[i]; }
        float mu  = ts * (1.f / 4096.f);
        float var = ts2 * (1.f / 4096.f) - mu * mu;
        rs[0]  = mu;
        rs2[0] = rsqrtf(var + EPS_GN);
    }
    __syncthreads();
    float mu = rs[0], rstd = rs2[0];

    float sc[4], bi[4];
#pragma unroll
    for (int c = 0; c < 4; c++) { sc[c] = scale[g * 4 + c]; bi[c] = bias[g * 4 + c]; }

    float* outy = out + (size_t)SP * 2;
    for (int j = threadIdx.x; j < H_ * W_ * 4; j += 256) {
        int yx = j >> 2, cl = j & 3;
        size_t idx = base + (size_t)yx * U_ + cl;
        float v = g_ys[idx];
        float h = (v - mu) * rstd * sc[cl] + bi[cl];
        float t = 0.7978845608028654f * (h + 0.044715f * h * h * h);
        outy[idx] = 0.5f * h * (1.f + tanhf(t));
    }
}

// ---------------- launch ----------------
extern "C" void kernel_launch(void* const* d_in, const int* in_sizes, int n_in,
                              void* d_out, int out_size) {
    const float* u_in  = (const float*)d_in[0];
    const float* x0    = (const float*)d_in[1];
    const float* Lre   = (const float*)d_in[2];
    const float* Lim   = (const float*)d_in[3];
    const float* B_ri  = (const float*)d_in[4];
    const float* C_ri  = (const float*)d_in[5];
    const float* lstep = (const float*)d_in[6];
    const float* Dk    = (const float*)d_in[7];
    const float* gsc   = (const float*)d_in[8];
    const float* gbi   = (const float*)d_in[9];
    float* out = (float*)d_out;
    (void)in_sizes; (void)n_in; (void)out_size;

    static bool attr_done = false;
    if (!attr_done) {
        cudaFuncSetAttribute(k_gemmB, cudaFuncAttributeMaxDynamicSharedMemorySize, 65536);
        cudaFuncSetAttribute(k_gemmC, cudaFuncAttributeMaxDynamicSharedMemorySize, 65536);
        attr_done = true;
    }

    k_pre<<<(NB_W + NC_W + 255) / 256, 256>>>(Lre, Lim, lstep, B_ri, C_ri);
    k_gemmB<<<dim3(4, 8, FRAMES), 256, 65536>>>(u_in);
    k_scan<<<SP / 256, 256>>>(x0, out);
    k_gemmC<<<dim3(8, FRAMES), 256, 65536>>>(0);
    k_dw<<<dim3(FRAMES, H_), 128>>>(u_in, Dk);
    k_gn<<<dim3(FRAMES, 32), 256>>>(gsc, gbi, out);
}

// round 4
// speedup vs baseline: 3.1928x; 1.0983x over previous
#include <cuda_runtime.h>
#include <cstdint>

// ---------------- problem constants ----------------
#define L_T   16
#define BSZ   8
#define H_    32
#define W_    32
#define U_    128
#define P_    256
#define FRAMES 128
#define SP    (BSZ*H_*W_*P_)      // 2,097,152
#define YS_N  (L_T*BSZ*H_*W_*U_)  // 16,777,216
#define BUS_N (L_T*BSZ*H_*W_*P_)  // 33,554,432
#define EPS_GN 1e-5f

#define NB_W  589824   // [chunk36][nb4][wn4][nt4][kk4][lane32][e2]
#define NC_W  589824   // [chunk144][wn4][nt4][kk4][lane32][e2]

// ---------------- device scratch (allocation-free) ----------------
__device__ __align__(16) float g_WB[NB_W];
__device__ __align__(16) float g_WC[NC_W];
__device__ float g_Are[P_];
__device__ float g_Aim[P_];
__device__ __align__(16) float g_Bus_re[BUS_N];
__device__ __align__(16) float g_Bus_im[BUS_N];
__device__ __align__(16) float g_ys[YS_N];

__device__ __forceinline__ uint32_t f2tf(float f) {
    uint32_t r; asm("cvt.rna.tf32.f32 %0, %1;" : "=r"(r) : "f"(f)); return r;
}

#define LDMX4(r0, r1, r2, r3, addr) \
    asm volatile("ldmatrix.sync.aligned.m8n8.x4.shared.b16 {%0,%1,%2,%3}, [%4];" \
                 : "=r"(r0), "=r"(r1), "=r"(r2), "=r"(r3) : "r"(addr))

#define MMA4(c, a0, a1, a2, a3, b) asm volatile( \
    "mma.sync.aligned.m16n8k8.row.col.f32.tf32.tf32.f32 " \
    "{%0,%1,%2,%3},{%4,%5,%6,%7},{%8,%9},{%0,%1,%2,%3};" \
    : "+f"((c)[0]), "+f"((c)[1]), "+f"((c)[2]), "+f"((c)[3]) \
    : "r"(a0), "r"(a1), "r"(a2), "r"(a3), "r"((b).x), "r"((b).y))

// ---------------- K0: discretization + weight fragment pre-permute ---------
__global__ void k_pre(const float* __restrict__ Lre, const float* __restrict__ Lim,
                      const float* __restrict__ lstep,
                      const float* __restrict__ B_ri, const float* __restrict__ C_ri) {
    int tid = blockIdx.x * blockDim.x + threadIdx.x;
    if (tid < P_) {
        float st = expf(lstep[tid]);
        g_Are[tid] = fminf(Lre[tid], -1e-4f) * st;
        g_Aim[tid] = Lim[tid] * st;
    }
    if (tid < NB_W) {
        int e = tid & 1, lane = (tid >> 1) & 31, kk = (tid >> 6) & 3;
        int nt = (tid >> 8) & 3, wn = (tid >> 10) & 3, nb = (tid >> 12) & 3;
        int chunk = tid >> 14;                       // 0..35
        int n = nb * 128 + wn * 32 + nt * 8 + (lane >> 2);
        int plane = n >> 8, p = n & 255;
        int tap = chunk >> 2;
        int c = (chunk & 3) * 32 + kk * 8 + (lane & 3) + 4 * e;
        float v = B_ri[(((size_t)p * 128 + c) * 9 + tap) * 2 + plane] * expf(lstep[p]);
        g_WB[tid] = __uint_as_float(f2tf(v));
    }
    int t2 = tid - NB_W;
    if (t2 >= 0 && t2 < NC_W) {
        int e = t2 & 1, lane = (t2 >> 1) & 31, kk = (t2 >> 6) & 3;
        int nt = (t2 >> 8) & 3, wn = (t2 >> 10) & 3;
        int chunk = t2 >> 12;                        // 0..143
        int u = wn * 32 + nt * 8 + (lane >> 2);
        int tap = chunk >> 4;
        int cidx = (chunk & 15) * 32 + kk * 8 + (lane & 3) + 4 * e;
        float v;
        if (cidx < 256) v =  2.f * C_ri[(((size_t)u * 256 + cidx) * 9 + tap) * 2];
        else            v = -2.f * C_ri[(((size_t)u * 256 + (cidx - 256)) * 9 + tap) * 2 + 1];
        g_WC[t2] = __uint_as_float(f2tf(v));
    }
}

// ------- shared GEMM machinery: A staged in smem (row-major + XOR swizzle) --
// A buffer: 128 rows x 128B (32 tf32). swizzled byte = row*128 + (c16 ^ ((row&7)<<4))
#define STS_A(buf) do { \
    uint32_t rb = abase + (buf) * 16384 + prow * 128; \
    _Pragma("unroll") \
    for (int q = 0; q < 4; q++) { \
        uint32_t a = rb + ((((phalf * 4 + q) * 16)) ^ ((prow & 7) << 4)); \
        asm volatile("st.shared.v4.b32 [%0],{%1,%2,%3,%4};" :: "r"(a), \
            "r"(f2tf(ld[q].x)), "r"(f2tf(ld[q].y)), "r"(f2tf(ld[q].z)), "r"(f2tf(ld[q].w))); \
    } \
} while (0)

#define COMP(buf, wp_chunk) do { \
    uint32_t bb = abase + (buf) * 16384; \
    _Pragma("unroll") \
    for (int kk = 0; kk < 4; kk++) { \
        uint2 b[4]; \
        const uint2* wp = (wp_chunk) + (size_t)kk * 32 + lane; \
        _Pragma("unroll") \
        for (int nt = 0; nt < 4; nt++) b[nt] = wp[nt * 128]; \
        _Pragma("unroll") \
        for (int mt = 0; mt < 4; mt++) { \
            uint32_t a0, a1, a2, a3; \
            uint32_t ad = bb + (wm * 64 + mt * 16 + lrow) * 128 + \
                          ((kk * 32 + lcol) ^ ((lrow & 7) << 4)); \
            LDMX4(a0, a1, a2, a3, ad); \
            _Pragma("unroll") \
            for (int nt = 0; nt < 4; nt++) MMA4(acc[mt][nt], a0, a1, a2, a3, b[nt]); \
        } \
    } \
} while (0)

// ---------------- GEMM B: Bus(re|im) = u (*) B_bar -------------------------
__global__ __launch_bounds__(256, 2) void k_gemmB(const float* __restrict__ u_in) {
    __shared__ __align__(16) float As[2][4096];
    int tid = threadIdx.x, lane = tid & 31, wid = tid >> 5;
    int wm = wid >> 2, wn = wid & 3;
    int g8 = lane >> 2, tig = lane & 3;
    int lrow = lane & 15, lcol = lane & 16;
    int prow = tid >> 1, phalf = tid & 1;
    int nb = blockIdx.x, slab = blockIdx.y, f = blockIdx.z;
    int y0 = slab * 4;
    uint32_t abase = (uint32_t)__cvta_generic_to_shared(&As[0][0]);

    float acc[4][4][4];
#pragma unroll
    for (int i = 0; i < 4; i++)
#pragma unroll
        for (int j = 0; j < 4; j++)
#pragma unroll
            for (int e = 0; e < 4; e++) acc[i][j][e] = 0.f;

    float4 ld[4];

#define LDG_B(k) do { \
    int tap = (k) >> 2; \
    int ky = tap / 3 - 1, kx = tap % 3 - 1; \
    int c0 = ((k) & 3) * 32 + phalf * 16; \
    int yy = y0 + (prow >> 5) + ky, xx = (prow & 31) + kx; \
    bool ok = ((unsigned)yy < 32u) && ((unsigned)xx < 32u); \
    const float4* src = (const float4*)(u_in + (((size_t)f * 32 + yy) * 32 + xx) * 128 + c0); \
    _Pragma("unroll") \
    for (int q = 0; q < 4; q++) ld[q] = ok ? src[q] : make_float4(0.f, 0.f, 0.f, 0.f); \
} while (0)

    LDG_B(0); STS_A(0); __syncthreads();
    for (int k = 0; k < 36; k++) {
        if (k + 1 < 36) LDG_B(k + 1);
        const uint2* wpc = (const uint2*)g_WB +
            ((((size_t)k * 4 + nb) * 4 + wn) * 16) * 32;
        COMP(k & 1, wpc);
        if (k + 1 < 36) STS_A((k + 1) & 1);
        __syncthreads();
    }

    float* base = (nb < 2) ? g_Bus_re : g_Bus_im;
    int ch0 = (nb & 1) * 128 + wn * 32;
#pragma unroll
    for (int mt = 0; mt < 4; mt++) {
        int m1 = wm * 64 + mt * 16 + g8, m2 = m1 + 8;
        size_t pix1 = (((size_t)f * 32 + y0 + (m1 >> 5)) * 32 + (m1 & 31)) * 256;
        size_t pix2 = (((size_t)f * 32 + y0 + (m2 >> 5)) * 32 + (m2 & 31)) * 256;
#pragma unroll
        for (int nt = 0; nt < 4; nt++) {
            int ch = ch0 + nt * 8 + tig * 2;
            *(float2*)(base + pix1 + ch) = make_float2(acc[mt][nt][0], acc[mt][nt][1]);
            *(float2*)(base + pix2 + ch) = make_float2(acc[mt][nt][2], acc[mt][nt][3]);
        }
    }
}

// ---------------- K2: diagonal complex scan --------------------------------
__global__ __launch_bounds__(256) void k_scan(const float* __restrict__ x0,
                                              float* __restrict__ out) {
    int s = blockIdx.x * 256 + threadIdx.x;
    int p = s & 255;
    float ar = g_Are[p], ai = g_Aim[p];
    float xr = x0[s], xi = 0.f;
    size_t idx = (size_t)s;
#pragma unroll
    for (int l = 0; l < L_T; l++, idx += SP) {
        float br = g_Bus_re[idx], bi = g_Bus_im[idx];
        float nr = fmaf(ar, xr, fmaf(-ai, xi, br));
        float ni = fmaf(ar, xi, fmaf(ai, xr, bi));
        xr = nr; xi = ni;
        g_Bus_re[idx] = xr;
        g_Bus_im[idx] = xi;
    }
    reinterpret_cast<float2*>(out)[s] = make_float2(xr, xi);
}

// ---------------- GEMM C: ys = 2Re(C (*) x) --------------------------------
__global__ __launch_bounds__(256, 2) void k_gemmC(int dummy) {
    __shared__ __align__(16) float As[2][4096];
    int tid = threadIdx.x, lane = tid & 31, wid = tid >> 5;
    int wm = wid >> 2, wn = wid & 3;
    int g8 = lane >> 2, tig = lane & 3;
    int lrow = lane & 15, lcol = lane & 16;
    int prow = tid >> 1, phalf = tid & 1;
    int slab = blockIdx.x, f = blockIdx.y;
    int y0 = slab * 4;
    uint32_t abase = (uint32_t)__cvta_generic_to_shared(&As[0][0]);

    float acc[4][4][4];
#pragma unroll
    for (int i = 0; i < 4; i++)
#pragma unroll
        for (int j = 0; j < 4; j++)
#pragma unroll
            for (int e = 0; e < 4; e++) acc[i][j][e] = 0.f;

    float4 ld[4];

#define LDG_C(k) do { \
    int tap = (k) >> 4, kc = (k) & 15; \
    const float* srcb = (kc < 8) ? g_Bus_re : g_Bus_im; \
    int ky = tap / 3 - 1, kx = tap % 3 - 1; \
    int c0 = (kc & 7) * 32 + phalf * 16; \
    int yy = y0 + (prow >> 5) + ky, xx = (prow & 31) + kx; \
    bool ok = ((unsigned)yy < 32u) && ((unsigned)xx < 32u); \
    const float4* src = (const float4*)(srcb + (((size_t)f * 32 + yy) * 32 + xx) * 256 + c0); \
    _Pragma("unroll") \
    for (int q = 0; q < 4; q++) ld[q] = ok ? src[q] : make_float4(0.f, 0.f, 0.f, 0.f); \
} while (0)

    LDG_C(0); STS_A(0); __syncthreads();
    for (int k = 0; k < 144; k++) {
        if (k + 1 < 144) LDG_C(k + 1);
        const uint2* wpc = (const uint2*)g_WC +
            (((size_t)k * 4 + wn) * 16) * 32;
        COMP(k & 1, wpc);
        if (k + 1 < 144) STS_A((k + 1) & 1);
        __syncthreads();
    }

#pragma unroll
    for (int mt = 0; mt < 4; mt++) {
        int m1 = wm * 64 + mt * 16 + g8, m2 = m1 + 8;
        size_t pix1 = (((size_t)f * 32 + y0 + (m1 >> 5)) * 32 + (m1 & 31)) * 128;
        size_t pix2 = (((size_t)f * 32 + y0 + (m2 >> 5)) * 32 + (m2 & 31)) * 128;
#pragma unroll
        for (int nt = 0; nt < 4; nt++) {
            int ch = wn * 32 + nt * 8 + tig * 2;
            *(float2*)(g_ys + pix1 + ch) = make_float2(acc[mt][nt][0], acc[mt][nt][1]);
            *(float2*)(g_ys + pix2 + ch) = make_float2(acc[mt][nt][2], acc[mt][nt][3]);
        }
    }
    (void)dummy;
}

// ---------------- K3b: depthwise D feedthrough -----------------------------
__global__ __launch_bounds__(128) void k_dw(const float* __restrict__ u_in,
                                            const float* __restrict__ Dk) {
    int f = blockIdx.x, y = blockIdx.y, u = threadIdx.x;
    float dk[9];
#pragma unroll
    for (int j = 0; j < 9; j++) dk[j] = Dk[j * U_ + u];
    float acc[W_];
#pragma unroll
    for (int x = 0; x < W_; x++) acc[x] = 0.f;
    for (int ky = 0; ky < 3; ky++) {
        int yi = y + ky - 1;
        if (yi < 0 || yi >= H_) continue;
        const float* row = u_in + ((size_t)(f * H_ + yi) * W_) * U_ + u;
        float v0 = 0.f, v1 = row[0];
#pragma unroll
        for (int x = 0; x < W_; x++) {
            float v2 = (x + 1 < W_) ? row[(x + 1) * U_] : 0.f;
            acc[x] = fmaf(v0, dk[ky * 3], fmaf(v1, dk[ky * 3 + 1], fmaf(v2, dk[ky * 3 + 2], acc[x])));
            v0 = v1; v1 = v2;
        }
    }
    size_t base = ((size_t)(f * H_ + y) * W_) * U_ + u;
#pragma unroll
    for (int x = 0; x < W_; x++) g_ys[base + (size_t)x * U_] += acc[x];
}

// ---------------- K4: GroupNorm(32) + tanh-GELU ----------------------------
__global__ __launch_bounds__(256) void k_gn(const float* __restrict__ scale,
                                            const float* __restrict__ bias,
                                            float* __restrict__ out) {
    int f = blockIdx.x, g = blockIdx.y;
    size_t base = (size_t)f * (H_ * W_ * U_) + g * 4;

    float s = 0.f, s2 = 0.f;
    for (int j = threadIdx.x; j < H_ * W_ * 4; j += 256) {
        int yx = j >> 2, cl = j & 3;
        float v = g_ys[base + (size_t)yx * U_ + cl];
        s += v; s2 += v * v;
    }
    __shared__ float rs[8], rs2[8];
    unsigned m = 0xffffffffu;
#pragma unroll
    for (int o = 16; o > 0; o >>= 1) {
        s  += __shfl_down_sync(m, s, o);
        s2 += __shfl_down_sync(m, s2, o);
    }
    if ((threadIdx.x & 31) == 0) { rs[threadIdx.x >> 5] = s; rs2[threadIdx.x >> 5] = s2; }
    __syncthreads();
    if (threadIdx.x == 0) {
        float ts = 0.f, ts2 = 0.f;
#pragma unroll
        for (int i = 0; i < 8; i++) { ts += rs[i]; ts2 += rs2[i]; }
        float mu  = ts * (1.f / 4096.f);
        float var = ts2 * (1.f / 4096.f) - mu * mu;
        rs[0]  = mu;
        rs2[0] = rsqrtf(var + EPS_GN);
    }
    __syncthreads();
    float mu = rs[0], rstd = rs2[0];

    float sc[4], bi[4];
#pragma unroll
    for (int c = 0; c < 4; c++) { sc[c] = scale[g * 4 + c]; bi[c] = bias[g * 4 + c]; }

    float* outy = out + (size_t)SP * 2;
    for (int j = threadIdx.x; j < H_ * W_ * 4; j += 256) {
        int yx = j >> 2, cl = j & 3;
        size_t idx = base + (size_t)yx * U_ + cl;
        float v = g_ys[idx];
        float h = (v - mu) * rstd * sc[cl] + bi[cl];
        float t = 0.7978845608028654f * (h + 0.044715f * h * h * h);
        outy[idx] = 0.5f * h * (1.f + tanhf(t));
    }
}

// ---------------- launch ----------------
extern "C" void kernel_launch(void* const* d_in, const int* in_sizes, int n_in,
                              void* d_out, int out_size) {
    const float* u_in  = (const float*)d_in[0];
    const float* x0    = (const float*)d_in[1];
    const float* Lre   = (const float*)d_in[2];
    const float* Lim   = (const float*)d_in[3];
    const float* B_ri  = (const float*)d_in[4];
    const float* C_ri  = (const float*)d_in[5];
    const float* lstep = (const float*)d_in[6];
    const float* Dk    = (const float*)d_in[7];
    const float* gsc   = (const float*)d_in[8];
    const float* gbi   = (const float*)d_in[9];
    float* out = (float*)d_out;
    (void)in_sizes; (void)n_in; (void)out_size;

    k_pre<<<(NB_W + NC_W + 255) / 256, 256>>>(Lre, Lim, lstep, B_ri, C_ri);
    k_gemmB<<<dim3(4, 8, FRAMES), 256>>>(u_in);
    k_scan<<<SP / 256, 256>>>(x0, out);
    k_gemmC<<<dim3(8, FRAMES), 256>>>(0);
    k_dw<<<dim3(FRAMES, H_), 128>>>(u_in, Dk);
    k_gn<<<dim3(FRAMES, 32), 256>>>(gsc, gbi, out);
}

// round 5
// speedup vs baseline: 3.9305x; 1.2311x over previous
#include <cuda_runtime.h>
#include <cstdint>

// ---------------- problem constants ----------------
#define L_T   16
#define BSZ   8
#define H_    32
#define W_    32
#define U_    128
#define P_    256
#define FRAMES 128
#define SP    (BSZ*H_*W_*P_)      // 2,097,152
#define YS_N  (L_T*BSZ*H_*W_*U_)  // 16,777,216
#define BUS_N (L_T*BSZ*H_*W_*P_)  // 33,554,432
#define U_N   (L_T*BSZ*H_*W_*U_)  // 16,777,216
#define EPS_GN 1e-5f

#define NB_W  589824   // [chunk36][nb4][wn4][nt4][kk4][lane32][e2]
#define NC_W  589824   // [chunk144][wn4][nt4][kk4][lane32][e2]

#define SMEM_GEMM 147456   // 3 stages x (32KB A + 16KB W)

// ---------------- device scratch (allocation-free) ----------------
__device__ __align__(16) float g_WB[NB_W];
__device__ __align__(16) float g_WC[NC_W];
__device__ float g_Are[P_];
__device__ float g_Aim[P_];
__device__ __align__(16) float g_u_tf[U_N];
__device__ __align__(16) float g_Bus_re[BUS_N];
__device__ __align__(16) float g_Bus_im[BUS_N];
__device__ __align__(16) float g_ys[YS_N];

__device__ __forceinline__ uint32_t f2tf(float f) {
    uint32_t r; asm("cvt.rna.tf32.f32 %0, %1;" : "=r"(r) : "f"(f)); return r;
}

#define LDMX4(r0, r1, r2, r3, addr) \
    asm volatile("ldmatrix.sync.aligned.m8n8.x4.shared.b16 {%0,%1,%2,%3}, [%4];" \
                 : "=r"(r0), "=r"(r1), "=r"(r2), "=r"(r3) : "r"(addr))

#define MMA4(c, a0, a1, a2, a3, b) asm volatile( \
    "mma.sync.aligned.m16n8k8.row.col.f32.tf32.tf32.f32 " \
    "{%0,%1,%2,%3},{%4,%5,%6,%7},{%8,%9},{%0,%1,%2,%3};" \
    : "+f"((c)[0]), "+f"((c)[1]), "+f"((c)[2]), "+f"((c)[3]) \
    : "r"(a0), "r"(a1), "r"(a2), "r"(a3), "r"((b).x), "r"((b).y))

#define CP16(dst, src, pred) do { \
    int _sz = (pred) ? 16 : 0; \
    asm volatile("cp.async.cg.shared.global [%0], [%1], 16, %2;" \
                 :: "r"(dst), "l"(src), "r"(_sz)); \
} while (0)

#define CP_COMMIT() asm volatile("cp.async.commit_group;" ::: "memory")
#define CP_WAIT2()  asm volatile("cp.async.wait_group 2;" ::: "memory")
#define CP_WAIT0()  asm volatile("cp.async.wait_group 0;" ::: "memory")

// ---------------- K0: discretization + weight fragment pre-permute ---------
__global__ void k_pre(const float* __restrict__ Lre, const float* __restrict__ Lim,
                      const float* __restrict__ lstep,
                      const float* __restrict__ B_ri, const float* __restrict__ C_ri) {
    int tid = blockIdx.x * blockDim.x + threadIdx.x;
    if (tid < P_) {
        float st = expf(lstep[tid]);
        g_Are[tid] = fminf(Lre[tid], -1e-4f) * st;
        g_Aim[tid] = Lim[tid] * st;
    }
    if (tid < NB_W) {
        int e = tid & 1, lane = (tid >> 1) & 31, kk = (tid >> 6) & 3;
        int nt = (tid >> 8) & 3, wn = (tid >> 10) & 3, nb = (tid >> 12) & 3;
        int chunk = tid >> 14;                       // 0..35
        int n = nb * 128 + wn * 32 + nt * 8 + (lane >> 2);
        int plane = n >> 8, p = n & 255;
        int tap = chunk >> 2;
        int c = (chunk & 3) * 32 + kk * 8 + (lane & 3) + 4 * e;
        float v = B_ri[(((size_t)p * 128 + c) * 9 + tap) * 2 + plane] * expf(lstep[p]);
        g_WB[tid] = __uint_as_float(f2tf(v));
    }
    int t2 = tid - NB_W;
    if (t2 >= 0 && t2 < NC_W) {
        int e = t2 & 1, lane = (t2 >> 1) & 31, kk = (t2 >> 6) & 3;
        int nt = (t2 >> 8) & 3, wn = (t2 >> 10) & 3;
        int chunk = t2 >> 12;                        // 0..143
        int u = wn * 32 + nt * 8 + (lane >> 2);
        int tap = chunk >> 4;
        int cidx = (chunk & 15) * 32 + kk * 8 + (lane & 3) + 4 * e;
        float v;
        if (cidx < 256) v =  2.f * C_ri[(((size_t)u * 256 + cidx) * 9 + tap) * 2];
        else            v = -2.f * C_ri[(((size_t)u * 256 + (cidx - 256)) * 9 + tap) * 2 + 1];
        g_WC[t2] = __uint_as_float(f2tf(v));
    }
}

// ---------------- K0b: round input to tf32 once ----------------------------
__global__ void k_round(const float* __restrict__ u_in) {
    int i = blockIdx.x * blockDim.x + threadIdx.x;   // float4 index
    const float4 v = ((const float4*)u_in)[i];
    uint4 t = make_uint4(f2tf(v.x), f2tf(v.y), f2tf(v.z), f2tf(v.w));
    ((uint4*)g_u_tf)[i] = t;
}

// ---------------- shared GEMM compute macro --------------------------------
#define COMP(s) do { \
    uint32_t ab = abase + (s) * 32768; \
    uint32_t wb = wbase + (s) * 16384; \
    _Pragma("unroll") \
    for (int kk = 0; kk < 4; kk++) { \
        uint2 b[4]; \
        _Pragma("unroll") \
        for (int nt = 0; nt < 4; nt++) { \
            uint32_t waddr = wb + ((((wn * 4 + nt) * 4 + kk) * 32 + lane) << 3); \
            asm volatile("ld.shared.v2.b32 {%0,%1}, [%2];" \
                         : "=r"(b[nt].x), "=r"(b[nt].y) : "r"(waddr)); \
        } \
        _Pragma("unroll") \
        for (int mt = 0; mt < 4; mt++) { \
            uint32_t a0, a1, a2, a3; \
            uint32_t ad = ab + (wm * 64 + mt * 16 + lrow) * 128 + \
                          ((kk * 32 + lcol) ^ ((lrow & 7) << 4)); \
            LDMX4(a0, a1, a2, a3, ad); \
            _Pragma("unroll") \
            for (int nt = 0; nt < 4; nt++) MMA4(acc[mt][nt], a0, a1, a2, a3, b[nt]); \
        } \
    } \
} while (0)

// ---------------- GEMM B: Bus(re|im) = u (*) B_bar -------------------------
// grid (nb4, slab4, f128), 512 thr. BM=256 (8 rows), BN=128, BK=32, 36 chunks.
__global__ __launch_bounds__(512, 1) void k_gemmB(int dummy) {
    extern __shared__ __align__(16) char smem[];
    int tid = threadIdx.x, lane = tid & 31, wid = tid >> 5;
    int wm = wid >> 2, wn = wid & 3;
    int g8 = lane >> 2, tig = lane & 3;
    int lrow = lane & 15, lcol = lane & 16;
    int nb = blockIdx.x, slab = blockIdx.y, f = blockIdx.z;
    int y0 = slab * 8;
    uint32_t abase = (uint32_t)__cvta_generic_to_shared(smem);
    uint32_t wbase = abase + 98304;

    float acc[4][4][4];
#pragma unroll
    for (int i = 0; i < 4; i++)
#pragma unroll
        for (int j = 0; j < 4; j++)
#pragma unroll
            for (int e = 0; e < 4; e++) acc[i][j][e] = 0.f;

#define ISSUE_B(s, k) do { \
    int tap = (k) >> 2; \
    int ky = tap / 3 - 1, kx = tap % 3 - 1; \
    int c0 = ((k) & 3) * 32; \
    _Pragma("unroll") \
    for (int q = 0; q < 4; q++) { \
        int idx = q * 512 + tid, m = idx >> 3, c16 = idx & 7; \
        int yy = y0 + (m >> 5) + ky, xx = (m & 31) + kx; \
        bool ok = ((unsigned)yy < 32u) && ((unsigned)xx < 32u); \
        const float* src = g_u_tf + ((((size_t)f * 32 + yy) * 32 + xx) << 7) + c0 + c16 * 4; \
        uint32_t dst = abase + (s) * 32768 + m * 128 + ((c16 * 16) ^ ((m & 7) << 4)); \
        CP16(dst, src, ok); \
    } \
    const float* wsrc = g_WB + (((size_t)(k) * 4 + nb) << 12); \
    _Pragma("unroll") \
    for (int q = 0; q < 2; q++) { \
        int idx = q * 512 + tid; \
        CP16(wbase + (s) * 16384 + idx * 16, wsrc + idx * 4, true); \
    } \
} while (0)

    ISSUE_B(0, 0); CP_COMMIT();
    ISSUE_B(1, 1); CP_COMMIT();
    for (int k = 0; k < 36; k++) {
        int s = k % 3;
        if (k + 2 < 36) { ISSUE_B((k + 2) % 3, k + 2); CP_COMMIT(); CP_WAIT2(); }
        else CP_WAIT0();
        __syncthreads();
        COMP(s);
        __syncthreads();
    }

    float* base = (nb < 2) ? g_Bus_re : g_Bus_im;
    int ch0 = (nb & 1) * 128 + wn * 32;
#pragma unroll
    for (int mt = 0; mt < 4; mt++) {
        int m1 = wm * 64 + mt * 16 + g8, m2 = m1 + 8;
        size_t pix1 = (((size_t)f * 32 + y0 + (m1 >> 5)) * 32 + (m1 & 31)) * 256;
        size_t pix2 = (((size_t)f * 32 + y0 + (m2 >> 5)) * 32 + (m2 & 31)) * 256;
#pragma unroll
        for (int nt = 0; nt < 4; nt++) {
            int ch = ch0 + nt * 8 + tig * 2;
            *(float2*)(base + pix1 + ch) = make_float2(acc[mt][nt][0], acc[mt][nt][1]);
            *(float2*)(base + pix2 + ch) = make_float2(acc[mt][nt][2], acc[mt][nt][3]);
        }
    }
    (void)dummy;
}

// ---------------- K2: diagonal complex scan (stores tf32-rounded xs) -------
__global__ __launch_bounds__(256) void k_scan(const float* __restrict__ x0,
                                              float* __restrict__ out) {
    int s = blockIdx.x * 256 + threadIdx.x;
    int p = s & 255;
    float ar = g_Are[p], ai = g_Aim[p];
    float xr = x0[s], xi = 0.f;
    size_t idx = (size_t)s;
#pragma unroll
    for (int l = 0; l < L_T; l++, idx += SP) {
        float br = g_Bus_re[idx], bi = g_Bus_im[idx];
        float nr = fmaf(ar, xr, fmaf(-ai, xi, br));
        float ni = fmaf(ar, xi, fmaf(ai, xr, bi));
        xr = nr; xi = ni;
        g_Bus_re[idx] = __uint_as_float(f2tf(xr));
        g_Bus_im[idx] = __uint_as_float(f2tf(xi));
    }
    reinterpret_cast<float2*>(out)[s] = make_float2(xr, xi);
}

// ---------------- GEMM C: ys = 2Re(C (*) x) --------------------------------
// grid (slab4, f128), 512 thr. BM=256, BN=128, 144 chunks.
__global__ __launch_bounds__(512, 1) void k_gemmC(int dummy) {
    extern __shared__ __align__(16) char smem[];
    int tid = threadIdx.x, lane = tid & 31, wid = tid >> 5;
    int wm = wid >> 2, wn = wid & 3;
    int g8 = lane >> 2, tig = lane & 3;
    int lrow = lane & 15, lcol = lane & 16;
    int slab = blockIdx.x, f = blockIdx.y;
    int y0 = slab * 8;
    uint32_t abase = (uint32_t)__cvta_generic_to_shared(smem);
    uint32_t wbase = abase + 98304;

    float acc[4][4][4];
#pragma unroll
    for (int i = 0; i < 4; i++)
#pragma unroll
        for (int j = 0; j < 4; j++)
#pragma unroll
            for (int e = 0; e < 4; e++) acc[i][j][e] = 0.f;

#define ISSUE_C(s, k) do { \
    int tap = (k) >> 4, kc = (k) & 15; \
    const float* srcb = (kc < 8) ? g_Bus_re : g_Bus_im; \
    int ky = tap / 3 - 1, kx = tap % 3 - 1; \
    int c0 = (kc & 7) * 32; \
    _Pragma("unroll") \
    for (int q = 0; q < 4; q++) { \
        int idx = q * 512 + tid, m = idx >> 3, c16 = idx & 7; \
        int yy = y0 + (m >> 5) + ky, xx = (m & 31) + kx; \
        bool ok = ((unsigned)yy < 32u) && ((unsigned)xx < 32u); \
        const float* src = srcb + ((((size_t)f * 32 + yy) * 32 + xx) << 8) + c0 + c16 * 4; \
        uint32_t dst = abase + (s) * 32768 + m * 128 + ((c16 * 16) ^ ((m & 7) << 4)); \
        CP16(dst, src, ok); \
    } \
    const float* wsrc = g_WC + ((size_t)(k) << 12); \
    _Pragma("unroll") \
    for (int q = 0; q < 2; q++) { \
        int idx = q * 512 + tid; \
        CP16(wbase + (s) * 16384 + idx * 16, wsrc + idx * 4, true); \
    } \
} while (0)

    ISSUE_C(0, 0); CP_COMMIT();
    ISSUE_C(1, 1); CP_COMMIT();
    for (int k = 0; k < 144; k++) {
        int s = k % 3;
        if (k + 2 < 144) { ISSUE_C((k + 2) % 3, k + 2); CP_COMMIT(); CP_WAIT2(); }
        else CP_WAIT0();
        __syncthreads();
        COMP(s);
        __syncthreads();
    }

#pragma unroll
    for (int mt = 0; mt < 4; mt++) {
        int m1 = wm * 64 + mt * 16 + g8, m2 = m1 + 8;
        size_t pix1 = (((size_t)f * 32 + y0 + (m1 >> 5)) * 32 + (m1 & 31)) * 128;
        size_t pix2 = (((size_t)f * 32 + y0 + (m2 >> 5)) * 32 + (m2 & 31)) * 128;
#pragma unroll
        for (int nt = 0; nt < 4; nt++) {
            int ch = wn * 32 + nt * 8 + tig * 2;
            *(float2*)(g_ys + pix1 + ch) = make_float2(acc[mt][nt][0], acc[mt][nt][1]);
            *(float2*)(g_ys + pix2 + ch) = make_float2(acc[mt][nt][2], acc[mt][nt][3]);
        }
    }
    (void)dummy;
}

// ---------------- K3b: depthwise D feedthrough -----------------------------
__global__ __launch_bounds__(128) void k_dw(const float* __restrict__ u_in,
                                            const float* __restrict__ Dk) {
    int f = blockIdx.x, y = blockIdx.y, u = threadIdx.x;
    float dk[9];
#pragma unroll
    for (int j = 0; j < 9; j++) dk[j] = Dk[j * U_ + u];
    float acc[W_];
#pragma unroll
    for (int x = 0; x < W_; x++) acc[x] = 0.f;
    for (int ky = 0; ky < 3; ky++) {
        int yi = y + ky - 1;
        if (yi < 0 || yi >= H_) continue;
        const float* row = u_in + ((size_t)(f * H_ + yi) * W_) * U_ + u;
        float v0 = 0.f, v1 = row[0];
#pragma unroll
        for (int x = 0; x < W_; x++) {
            float v2 = (x + 1 < W_) ? row[(x + 1) * U_] : 0.f;
            acc[x] = fmaf(v0, dk[ky * 3], fmaf(v1, dk[ky * 3 + 1], fmaf(v2, dk[ky * 3 + 2], acc[x])));
            v0 = v1; v1 = v2;
        }
    }
    size_t base = ((size_t)(f * H_ + y) * W_) * U_ + u;
#pragma unroll
    for (int x = 0; x < W_; x++) g_ys[base + (size_t)x * U_] += acc[x];
}

// ---------------- K4: GroupNorm(32) + tanh-GELU ----------------------------
__global__ __launch_bounds__(256) void k_gn(const float* __restrict__ scale,
                                            const float* __restrict__ bias,
                                            float* __restrict__ out) {
    int f = blockIdx.x, g = blockIdx.y;
    size_t base = (size_t)f * (H_ * W_ * U_) + g * 4;

    float s = 0.f, s2 = 0.f;
    for (int j = threadIdx.x; j < H_ * W_ * 4; j += 256) {
        int yx = j >> 2, cl = j & 3;
        float v = g_ys[base + (size_t)yx * U_ + cl];
        s += v; s2 += v * v;
    }
    __shared__ float rs[8], rs2[8];
    unsigned m = 0xffffffffu;
#pragma unroll
    for (int o = 16; o > 0; o >>= 1) {
        s  += __shfl_down_sync(m, s, o);
        s2 += __shfl_down_sync(m, s2, o);
    }
    if ((threadIdx.x & 31) == 0) { rs[threadIdx.x >> 5] = s; rs2[threadIdx.x >> 5] = s2; }
    __syncthreads();
    if (threadIdx.x == 0) {
        float ts = 0.f, ts2 = 0.f;
#pragma unroll
        for (int i = 0; i < 8; i++) { ts += rs[i]; ts2 += rs2[i]; }
        float mu  = ts * (1.f / 4096.f);
        float var = ts2 * (1.f / 4096.f) - mu * mu;
        rs[0]  = mu;
        rs2[0] = rsqrtf(var + EPS_GN);
    }
    __syncthreads();
    float mu = rs[0], rstd = rs2[0];

    float sc[4], bi[4];
#pragma unroll
    for (int c = 0; c < 4; c++) { sc[c] = scale[g * 4 + c]; bi[c] = bias[g * 4 + c]; }

    float* outy = out + (size_t)SP * 2;
    for (int j = threadIdx.x; j < H_ * W_ * 4; j += 256) {
        int yx = j >> 2, cl = j & 3;
        size_t idx = base + (size_t)yx * U_ + cl;
        float v = g_ys[idx];
        float h = (v - mu) * rstd * sc[cl] + bi[cl];
        float t = 0.7978845608028654f * (h + 0.044715f * h * h * h);
        outy[idx] = 0.5f * h * (1.f + tanhf(t));
    }
}

// ---------------- launch ----------------
extern "C" void kernel_launch(void* const* d_in, const int* in_sizes, int n_in,
                              void* d_out, int out_size) {
    const float* u_in  = (const float*)d_in[0];
    const float* x0    = (const float*)d_in[1];
    const float* Lre   = (const float*)d_in[2];
    const float* Lim   = (const float*)d_in[3];
    const float* B_ri  = (const float*)d_in[4];
    const float* C_ri  = (const float*)d_in[5];
    const float* lstep = (const float*)d_in[6];
    const float* Dk    = (const float*)d_in[7];
    const float* gsc   = (const float*)d_in[8];
    const float* gbi   = (const float*)d_in[9];
    float* out = (float*)d_out;
    (void)in_sizes; (void)n_in; (void)out_size;

    cudaFuncSetAttribute(k_gemmB, cudaFuncAttributeMaxDynamicSharedMemorySize, SMEM_GEMM);
    cudaFuncSetAttribute(k_gemmC, cudaFuncAttributeMaxDynamicSharedMemorySize, SMEM_GEMM);

    k_pre<<<(NB_W + NC_W + 255) / 256, 256>>>(Lre, Lim, lstep, B_ri, C_ri);
    k_round<<<U_N / 4 / 256, 256>>>(u_in);
    k_gemmB<<<dim3(4, 4, FRAMES), 512, SMEM_GEMM>>>(0);
    k_scan<<<SP / 256, 256>>>(x0, out);
    k_gemmC<<<dim3(4, FRAMES), 512, SMEM_GEMM>>>(0);
    k_dw<<<dim3(FRAMES, H_), 128>>>(u_in, Dk);
    k_gn<<<dim3(FRAMES, 32), 256>>>(gsc, gbi, out);
}

// round 6
// speedup vs baseline: 6.9794x; 1.7757x over previous
#include <cuda_runtime.h>
#include <cuda_fp16.h>
#include <cstdint>

// ---------------- problem constants ----------------
#define L_T   16
#define BSZ   8
#define H_    32
#define W_    32
#define U_    128
#define P_    256
#define FRAMES 128
#define SP    (BSZ*H_*W_*P_)      // 2,097,152
#define YS_N  (L_T*BSZ*H_*W_*U_)  // 16,777,216
#define BUS_N (L_T*BSZ*H_*W_*P_)  // 33,554,432
#define U_N   (L_T*BSZ*H_*W_*U_)  // 16,777,216
#define EPS_GN 1e-5f

#define NB_W  589824   // half: [chunk18][nb4][wn4][nt4][ks4][lane32][reg2][h2]
#define NC_W  589824   // half: [chunk72][wn4][nt4][ks4][lane32][reg2][h2]

#define SMEM_GEMM 147456   // 3 stages x (32KB A + 16KB W)

// ---------------- device scratch (allocation-free) ----------------
__device__ __align__(16) __half g_WBh[NB_W];
__device__ __align__(16) __half g_WCh[NC_W];
__device__ float g_Are[P_];
__device__ float g_Aim[P_];
__device__ __align__(16) __half g_u_h[U_N];
__device__ __align__(16) float g_Bus_re[BUS_N];
__device__ __align__(16) float g_Bus_im[BUS_N];
__device__ __align__(16) __half g_xh_re[BUS_N];
__device__ __align__(16) __half g_xh_im[BUS_N];
__device__ __align__(16) float g_ys[YS_N];

#define LDMX4(r0, r1, r2, r3, addr) \
    asm volatile("ldmatrix.sync.aligned.m8n8.x4.shared.b16 {%0,%1,%2,%3}, [%4];" \
                 : "=r"(r0), "=r"(r1), "=r"(r2), "=r"(r3) : "r"(addr))

#define MMAH(c, a0, a1, a2, a3, b) asm volatile( \
    "mma.sync.aligned.m16n8k16.row.col.f32.f16.f16.f32 " \
    "{%0,%1,%2,%3},{%4,%5,%6,%7},{%8,%9},{%0,%1,%2,%3};" \
    : "+f"((c)[0]), "+f"((c)[1]), "+f"((c)[2]), "+f"((c)[3]) \
    : "r"(a0), "r"(a1), "r"(a2), "r"(a3), "r"((b).x), "r"((b).y))

#define CP16(dst, src, pred) do { \
    int _sz = (pred) ? 16 : 0; \
    asm volatile("cp.async.cg.shared.global [%0], [%1], 16, %2;" \
                 :: "r"(dst), "l"(src), "r"(_sz)); \
} while (0)

#define CP_COMMIT() asm volatile("cp.async.commit_group;" ::: "memory")
#define CP_WAIT2()  asm volatile("cp.async.wait_group 2;" ::: "memory")
#define CP_WAIT0()  asm volatile("cp.async.wait_group 0;" ::: "memory")

// ---------------- K0: discretization + weight fragment pre-permute (half) --
__global__ void k_pre(const float* __restrict__ Lre, const float* __restrict__ Lim,
                      const float* __restrict__ lstep,
                      const float* __restrict__ B_ri, const float* __restrict__ C_ri) {
    int tid = blockIdx.x * blockDim.x + threadIdx.x;
    if (tid < P_) {
        float st = expf(lstep[tid]);
        g_Are[tid] = fminf(Lre[tid], -1e-4f) * st;
        g_Aim[tid] = Lim[tid] * st;
    }
    if (tid < NB_W) {
        int h = tid & 1, reg = (tid >> 1) & 1, lane = (tid >> 2) & 31;
        int ks = (tid >> 7) & 3, nt = (tid >> 9) & 3, wn = (tid >> 11) & 3;
        int nb = (tid >> 13) & 3, chunk = tid >> 15;            // 0..17
        int kch = ks * 16 + reg * 8 + (lane & 3) * 2 + h;
        int tap = chunk >> 1, cb = chunk & 1;
        int c = cb * 64 + kch;
        int n = nb * 128 + wn * 32 + nt * 8 + (lane >> 2);
        int plane = n >> 8, p = n & 255;
        float v = B_ri[(((size_t)p * 128 + c) * 9 + tap) * 2 + plane] * expf(lstep[p]);
        g_WBh[tid] = __float2half_rn(v);
    }
    int t2 = tid - NB_W;
    if (t2 >= 0 && t2 < NC_W) {
        int h = t2 & 1, reg = (t2 >> 1) & 1, lane = (t2 >> 2) & 31;
        int ks = (t2 >> 7) & 3, nt = (t2 >> 9) & 3, wn = (t2 >> 11) & 3;
        int chunk = t2 >> 13;                                   // 0..71
        int kch = ks * 16 + reg * 8 + (lane & 3) * 2 + h;
        int tap = chunk >> 3, kc8 = chunk & 7;
        int cidx = kc8 * 64 + kch;
        int u = wn * 32 + nt * 8 + (lane >> 2);
        float v;
        if (cidx < 256) v =  2.f * C_ri[(((size_t)u * 256 + cidx) * 9 + tap) * 2];
        else            v = -2.f * C_ri[(((size_t)u * 256 + (cidx - 256)) * 9 + tap) * 2 + 1];
        g_WCh[t2] = __float2half_rn(v);
    }
}

// ---------------- K0b: input f32 -> half -----------------------------------
__global__ void k_uh(const float* __restrict__ u_in) {
    int i = blockIdx.x * blockDim.x + threadIdx.x;   // groups of 4 floats
    float4 v = ((const float4*)u_in)[i];
    __half2* dst = (__half2*)g_u_h;
    dst[2 * i]     = __floats2half2_rn(v.x, v.y);
    dst[2 * i + 1] = __floats2half2_rn(v.z, v.w);
}

// ---------------- shared GEMM compute macro (fp16, BK=64) ------------------
#define COMP(s) do { \
    uint32_t ab = abase + (s) * 32768; \
    uint32_t wb = wbase + (s) * 16384; \
    _Pragma("unroll") \
    for (int ks = 0; ks < 4; ks++) { \
        uint2 b[4]; \
        _Pragma("unroll") \
        for (int nt = 0; nt < 4; nt++) { \
            uint32_t waddr = wb + ((((wn * 4 + nt) * 4 + ks) * 32 + lane) << 3); \
            asm volatile("ld.shared.v2.b32 {%0,%1}, [%2];" \
                         : "=r"(b[nt].x), "=r"(b[nt].y) : "r"(waddr)); \
        } \
        _Pragma("unroll") \
        for (int mt = 0; mt < 4; mt++) { \
            uint32_t a0, a1, a2, a3; \
            uint32_t ad = ab + (wm * 64 + mt * 16 + lrow) * 128 + \
                          ((ks * 32 + lcol) ^ ((lrow & 7) << 4)); \
            LDMX4(a0, a1, a2, a3, ad); \
            _Pragma("unroll") \
            for (int nt = 0; nt < 4; nt++) MMAH(acc[mt][nt], a0, a1, a2, a3, b[nt]); \
        } \
    } \
} while (0)

// ---------------- GEMM B: Bus(re|im) = u (*) B_bar -------------------------
// grid (nb4, slab4, f128), 512 thr. BM=256 px, BN=128, BK=64, 18 chunks.
__global__ __launch_bounds__(512, 1) void k_gemmB(int dummy) {
    extern __shared__ __align__(16) char smem[];
    int tid = threadIdx.x, lane = tid & 31, wid = tid >> 5;
    int wm = wid >> 2, wn = wid & 3;
    int g8 = lane >> 2, tig = lane & 3;
    int lrow = lane & 15, lcol = lane & 16;
    int nb = blockIdx.x, slab = blockIdx.y, f = blockIdx.z;
    int y0 = slab * 8;
    uint32_t abase = (uint32_t)__cvta_generic_to_shared(smem);
    uint32_t wbase = abase + 98304;

    float acc[4][4][4];
#pragma unroll
    for (int i = 0; i < 4; i++)
#pragma unroll
        for (int j = 0; j < 4; j++)
#pragma unroll
            for (int e = 0; e < 4; e++) acc[i][j][e] = 0.f;

#define ISSUE_B(s, k) do { \
    int tap = (k) >> 1, cb = (k) & 1; \
    int ky = tap / 3 - 1, kx = tap % 3 - 1; \
    _Pragma("unroll") \
    for (int q = 0; q < 4; q++) { \
        int idx = q * 512 + tid, m = idx >> 3, c8 = idx & 7; \
        int yy = y0 + (m >> 5) + ky, xx = (m & 31) + kx; \
        bool ok = ((unsigned)yy < 32u) && ((unsigned)xx < 32u); \
        const __half* src = g_u_h + ((((size_t)f * 32 + yy) * 32 + xx) << 7) + cb * 64 + c8 * 8; \
        uint32_t dst = abase + (s) * 32768 + m * 128 + ((c8 * 16) ^ ((m & 7) << 4)); \
        CP16(dst, src, ok); \
    } \
    const __half* wsrc = g_WBh + (((size_t)(k) * 4 + nb) << 13); \
    _Pragma("unroll") \
    for (int q = 0; q < 2; q++) { \
        int idx = q * 512 + tid; \
        CP16(wbase + (s) * 16384 + idx * 16, wsrc + idx * 8, true); \
    } \
} while (0)

    ISSUE_B(0, 0); CP_COMMIT();
    ISSUE_B(1, 1); CP_COMMIT();
    for (int k = 0; k < 18; k++) {
        int s = k % 3;
        if (k + 2 < 18) { ISSUE_B((k + 2) % 3, k + 2); CP_COMMIT(); CP_WAIT2(); }
        else CP_WAIT0();
        __syncthreads();
        COMP(s);
        __syncthreads();
    }

    float* base = (nb < 2) ? g_Bus_re : g_Bus_im;
    int ch0 = (nb & 1) * 128 + wn * 32;
#pragma unroll
    for (int mt = 0; mt < 4; mt++) {
        int m1 = wm * 64 + mt * 16 + g8, m2 = m1 + 8;
        size_t pix1 = (((size_t)f * 32 + y0 + (m1 >> 5)) * 32 + (m1 & 31)) * 256;
        size_t pix2 = (((size_t)f * 32 + y0 + (m2 >> 5)) * 32 + (m2 & 31)) * 256;
#pragma unroll
        for (int nt = 0; nt < 4; nt++) {
            int ch = ch0 + nt * 8 + tig * 2;
            *(float2*)(base + pix1 + ch) = make_float2(acc[mt][nt][0], acc[mt][nt][1]);
            *(float2*)(base + pix2 + ch) = make_float2(acc[mt][nt][2], acc[mt][nt][3]);
        }
    }
    (void)dummy;
}

// ---------------- K2: scan; writes half xs planes + f32 x_last -------------
__global__ __launch_bounds__(256) void k_scan(const float* __restrict__ x0,
                                              float* __restrict__ out) {
    int s = blockIdx.x * 256 + threadIdx.x;
    int p = s & 255;
    float ar = g_Are[p], ai = g_Aim[p];
    float xr = x0[s], xi = 0.f;
    size_t idx = (size_t)s;
#pragma unroll
    for (int l = 0; l < L_T; l++, idx += SP) {
        float br = g_Bus_re[idx], bi = g_Bus_im[idx];
        float nr = fmaf(ar, xr, fmaf(-ai, xi, br));
        float ni = fmaf(ar, xi, fmaf(ai, xr, bi));
        xr = nr; xi = ni;
        g_xh_re[idx] = __float2half_rn(xr);
        g_xh_im[idx] = __float2half_rn(xi);
    }
    reinterpret_cast<float2*>(out)[s] = make_float2(xr, xi);
}

// ---------------- GEMM C: ys = 2Re(C (*) x) --------------------------------
// grid (slab4, f128), 512 thr. BM=256, BN=128, BK=64, 72 chunks.
__global__ __launch_bounds__(512, 1) void k_gemmC(int dummy) {
    extern __shared__ __align__(16) char smem[];
    int tid = threadIdx.x, lane = tid & 31, wid = tid >> 5;
    int wm = wid >> 2, wn = wid & 3;
    int g8 = lane >> 2, tig = lane & 3;
    int lrow = lane & 15, lcol = lane & 16;
    int slab = blockIdx.x, f = blockIdx.y;
    int y0 = slab * 8;
    uint32_t abase = (uint32_t)__cvta_generic_to_shared(smem);
    uint32_t wbase = abase + 98304;

    float acc[4][4][4];
#pragma unroll
    for (int i = 0; i < 4; i++)
#pragma unroll
        for (int j = 0; j < 4; j++)
#pragma unroll
            for (int e = 0; e < 4; e++) acc[i][j][e] = 0.f;

#define ISSUE_C(s, k) do { \
    int tap = (k) >> 3, kc8 = (k) & 7; \
    const __half* srcb = (kc8 < 4) ? g_xh_re : g_xh_im; \
    int c0 = (kc8 & 3) * 64; \
    int ky = tap / 3 - 1, kx = tap % 3 - 1; \
    _Pragma("unroll") \
    for (int q = 0; q < 4; q++) { \
        int idx = q * 512 + tid, m = idx >> 3, c8 = idx & 7; \
        int yy = y0 + (m >> 5) + ky, xx = (m & 31) + kx; \
        bool ok = ((unsigned)yy < 32u) && ((unsigned)xx < 32u); \
        const __half* src = srcb + ((((size_t)f * 32 + yy) * 32 + xx) << 8) + c0 + c8 * 8; \
        uint32_t dst = abase + (s) * 32768 + m * 128 + ((c8 * 16) ^ ((m & 7) << 4)); \
        CP16(dst, src, ok); \
    } \
    const __half* wsrc = g_WCh + ((size_t)(k) << 13); \
    _Pragma("unroll") \
    for (int q = 0; q < 2; q++) { \
        int idx = q * 512 + tid; \
        CP16(wbase + (s) * 16384 + idx * 16, wsrc + idx * 8, true); \
    } \
} while (0)

    ISSUE_C(0, 0); CP_COMMIT();
    ISSUE_C(1, 1); CP_COMMIT();
    for (int k = 0; k < 72; k++) {
        int s = k % 3;
        if (k + 2 < 72) { ISSUE_C((k + 2) % 3, k + 2); CP_COMMIT(); CP_WAIT2(); }
        else CP_WAIT0();
        __syncthreads();
        COMP(s);
        __syncthreads();
    }

#pragma unroll
    for (int mt = 0; mt < 4; mt++) {
        int m1 = wm * 64 + mt * 16 + g8, m2 = m1 + 8;
        size_t pix1 = (((size_t)f * 32 + y0 + (m1 >> 5)) * 32 + (m1 & 31)) * 128;
        size_t pix2 = (((size_t)f * 32 + y0 + (m2 >> 5)) * 32 + (m2 & 31)) * 128;
#pragma unroll
        for (int nt = 0; nt < 4; nt++) {
            int ch = wn * 32 + nt * 8 + tig * 2;
            *(float2*)(g_ys + pix1 + ch) = make_float2(acc[mt][nt][0], acc[mt][nt][1]);
            *(float2*)(g_ys + pix2 + ch) = make_float2(acc[mt][nt][2], acc[mt][nt][3]);
        }
    }
    (void)dummy;
}

// ---------------- K3b: depthwise D feedthrough (f32) -----------------------
__global__ __launch_bounds__(128) void k_dw(const float* __restrict__ u_in,
                                            const float* __restrict__ Dk) {
    int f = blockIdx.x, y = blockIdx.y, u = threadIdx.x;
    float dk[9];
#pragma unroll
    for (int j = 0; j < 9; j++) dk[j] = Dk[j * U_ + u];
    float acc[W_];
#pragma unroll
    for (int x = 0; x < W_; x++) acc[x] = 0.f;
    for (int ky = 0; ky < 3; ky++) {
        int yi = y + ky - 1;
        if (yi < 0 || yi >= H_) continue;
        const float* row = u_in + ((size_t)(f * H_ + yi) * W_) * U_ + u;
        float v0 = 0.f, v1 = row[0];
#pragma unroll
        for (int x = 0; x < W_; x++) {
            float v2 = (x + 1 < W_) ? row[(x + 1) * U_] : 0.f;
            acc[x] = fmaf(v0, dk[ky * 3], fmaf(v1, dk[ky * 3 + 1], fmaf(v2, dk[ky * 3 + 2], acc[x])));
            v0 = v1; v1 = v2;
        }
    }
    size_t base = ((size_t)(f * H_ + y) * W_) * U_ + u;
#pragma unroll
    for (int x = 0; x < W_; x++) g_ys[base + (size_t)x * U_] += acc[x];
}

// ---------------- K4: GroupNorm(32) + tanh-GELU ----------------------------
__global__ __launch_bounds__(256) void k_gn(const float* __restrict__ scale,
                                            const float* __restrict__ bias,
                                            float* __restrict__ out) {
    int f = blockIdx.x, g = blockIdx.y;
    size_t base = (size_t)f * (H_ * W_ * U_) + g * 4;

    float s = 0.f, s2 = 0.f;
    for (int j = threadIdx.x; j < H_ * W_ * 4; j += 256) {
        int yx = j >> 2, cl = j & 3;
        float v = g_ys[base + (size_t)yx * U_ + cl];
        s += v; s2 += v * v;
    }
    __shared__ float rs[8], rs2[8];
    unsigned m = 0xffffffffu;
#pragma unroll
    for (int o = 16; o > 0; o >>= 1) {
        s  += __shfl_down_sync(m, s, o);
        s2 += __shfl_down_sync(m, s2, o);
    }
    if ((threadIdx.x & 31) == 0) { rs[threadIdx.x >> 5] = s; rs2[threadIdx.x >> 5] = s2; }
    __syncthreads();
    if (threadIdx.x == 0) {
        float ts = 0.f, ts2 = 0.f;
#pragma unroll
        for (int i = 0; i < 8; i++) { ts += rs[i]; ts2 += rs2[i]; }
        float mu  = ts * (1.f / 4096.f);
        float var = ts2 * (1.f / 4096.f) - mu * mu;
        rs[0]  = mu;
        rs2[0] = rsqrtf(var + EPS_GN);
    }
    __syncthreads();
    float mu = rs[0], rstd = rs2[0];

    float sc[4], bi[4];
#pragma unroll
    for (int c = 0; c < 4; c++) { sc[c] = scale[g * 4 + c]; bi[c] = bias[g * 4 + c]; }

    float* outy = out + (size_t)SP * 2;
    for (int j = threadIdx.x; j < H_ * W_ * 4; j += 256) {
        int yx = j >> 2, cl = j & 3;
        size_t idx = base + (size_t)yx * U_ + cl;
        float v = g_ys[idx];
        float h = (v - mu) * rstd * sc[cl] + bi[cl];
        float t = 0.7978845608028654f * (h + 0.044715f * h * h * h);
        outy[idx] = 0.5f * h * (1.f + tanhf(t));
    }
}

// ---------------- launch ----------------
extern "C" void kernel_launch(void* const* d_in, const int* in_sizes, int n_in,
                              void* d_out, int out_size) {
    const float* u_in  = (const float*)d_in[0];
    const float* x0    = (const float*)d_in[1];
    const float* Lre   = (const float*)d_in[2];
    const float* Lim   = (const float*)d_in[3];
    const float* B_ri  = (const float*)d_in[4];
    const float* C_ri  = (const float*)d_in[5];
    const float* lstep = (const float*)d_in[6];
    const float* Dk    = (const float*)d_in[7];
    const float* gsc   = (const float*)d_in[8];
    const float* gbi   = (const float*)d_in[9];
    float* out = (float*)d_out;
    (void)in_sizes; (void)n_in; (void)out_size;

    cudaFuncSetAttribute(k_gemmB, cudaFuncAttributeMaxDynamicSharedMemorySize, SMEM_GEMM);
    cudaFuncSetAttribute(k_gemmC, cudaFuncAttributeMaxDynamicSharedMemorySize, SMEM_GEMM);

    k_pre<<<(NB_W + NC_W + 255) / 256, 256>>>(Lre, Lim, lstep, B_ri, C_ri);
    k_uh<<<U_N / 4 / 256, 256>>>(u_in);
    k_gemmB<<<dim3(4, 4, FRAMES), 512, SMEM_GEMM>>>(0);
    k_scan<<<SP / 256, 256>>>(x0, out);
    k_gemmC<<<dim3(4, FRAMES), 512, SMEM_GEMM>>>(0);
    k_dw<<<dim3(FRAMES, H_), 128>>>(u_in, Dk);
    k_gn<<<dim3(FRAMES, 32), 256>>>(gsc, gbi, out);
}